// round 1
// baseline (speedup 1.0000x reference)
#include <cuda_runtime.h>
#include <math.h>
#include <stdint.h>

// Problem dims (fixed for this problem instance)
#define BSZ 4
#define SEQ 2048
#define DIM 1024
#define NH  16
#define DH  64

// ---------------------------------------------------------------------------
// Scratch (device globals; no allocations allowed)
// ---------------------------------------------------------------------------
__device__ float g_q  [(size_t)BSZ*NH*SEQ*DH];   // [b,h,s,d]  32 MB
__device__ float g_k  [(size_t)BSZ*NH*SEQ*DH];   // [b,h,s,d]  32 MB
__device__ float g_vt [(size_t)BSZ*NH*DH*SEQ];   // [b,h,d,s]  32 MB (V transposed)
__device__ float g_w  [(size_t)BSZ*NH*SEQ*SEQ];  // attn weights, 1 GiB
__device__ float g_ctx[(size_t)BSZ*SEQ*DIM];     // [b,s,dim]  32 MB

// Output-mapping modes for the generic GEMM epilogue
#define OUT_PLAIN 0   // C[z*strideCz + m*N + n]
#define OUT_QHEAD 1   // [b,h,s,d] from m=(b,s), n=(h,d)
#define OUT_VT    2   // [b,h,d,s] from m=(b,s), n=(h,d)
#define OUT_CTX   3   // ctx[b,s,h*64+d] from z=(b,h), m=q, n=d

// ---------------------------------------------------------------------------
// Generic tiled SGEMM:  C = (A[M,K] @ B[N,K]^T + bias) * scale
// Both operands row-major with K contiguous. All dims divide tile sizes.
// ---------------------------------------------------------------------------
template<int BM, int BN, int BK, int TM, int TN, int MODE>
__global__ void __launch_bounds__((BM/TM)*(BN/TN))
sgemm_tn(const float* __restrict__ Ag, const float* __restrict__ Bg,
         const float* __restrict__ bias, float* __restrict__ Cg,
         int M, int N, int K, float scale,
         size_t strideAz, size_t strideBz, size_t strideCz)
{
    constexpr int NT = (BM/TM)*(BN/TN);
    __shared__ float As[BK][BM];
    __shared__ float Bs[BK][BN];

    const int z   = blockIdx.z;
    const float* A = Ag + (size_t)z * strideAz;
    const float* B = Bg + (size_t)z * strideBz;

    const int bm0 = blockIdx.y * BM;
    const int bn0 = blockIdx.x * BN;
    const int tid = threadIdx.x;
    const int tx  = tid % (BN/TN);
    const int ty  = tid / (BN/TN);

    float acc[TM][TN];
    #pragma unroll
    for (int i = 0; i < TM; i++)
        #pragma unroll
        for (int j = 0; j < TN; j++) acc[i][j] = 0.f;

    float ar[TM], br[TN];

    for (int k0 = 0; k0 < K; k0 += BK) {
        // Load A tile (BM rows x BK cols), store transposed into As
        for (int i = tid; i < BM*BK/4; i += NT) {
            int row = i / (BK/4);
            int c4  = (i % (BK/4)) * 4;
            float4 v = *reinterpret_cast<const float4*>(
                &A[(size_t)(bm0 + row) * K + k0 + c4]);
            As[c4+0][row] = v.x; As[c4+1][row] = v.y;
            As[c4+2][row] = v.z; As[c4+3][row] = v.w;
        }
        // Load B tile (BN rows x BK cols), store transposed into Bs
        for (int i = tid; i < BN*BK/4; i += NT) {
            int row = i / (BK/4);
            int c4  = (i % (BK/4)) * 4;
            float4 v = *reinterpret_cast<const float4*>(
                &B[(size_t)(bn0 + row) * K + k0 + c4]);
            Bs[c4+0][row] = v.x; Bs[c4+1][row] = v.y;
            Bs[c4+2][row] = v.z; Bs[c4+3][row] = v.w;
        }
        __syncthreads();

        #pragma unroll
        for (int kk = 0; kk < BK; kk++) {
            #pragma unroll
            for (int i = 0; i < TM; i++) ar[i] = As[kk][ty*TM + i];
            #pragma unroll
            for (int j = 0; j < TN; j++) br[j] = Bs[kk][tx*TN + j];
            #pragma unroll
            for (int i = 0; i < TM; i++)
                #pragma unroll
                for (int j = 0; j < TN; j++)
                    acc[i][j] += ar[i] * br[j];
        }
        __syncthreads();
    }

    // Epilogue
    #pragma unroll
    for (int i = 0; i < TM; i++) {
        const int m = bm0 + ty*TM + i;
        #pragma unroll
        for (int j = 0; j < TN; j++) {
            const int n = bn0 + tx*TN + j;
            float v = acc[i][j];
            if (bias) v += bias[n];
            v *= scale;
            size_t idx;
            if (MODE == OUT_PLAIN) {
                idx = (size_t)z * strideCz + (size_t)m * N + n;
            } else if (MODE == OUT_QHEAD) {
                int b = m >> 11, s = m & (SEQ-1);
                int h = n >> 6,  d = n & (DH-1);
                idx = (((size_t)(b*NH + h) * SEQ) + s) * DH + d;
            } else if (MODE == OUT_VT) {
                int b = m >> 11, s = m & (SEQ-1);
                int h = n >> 6,  d = n & (DH-1);
                idx = (((size_t)(b*NH + h) * DH) + d) * SEQ + s;
            } else { // OUT_CTX
                int b = z / NH, h = z % NH;
                idx = ((size_t)(b*SEQ + m)) * DIM + (size_t)h*DH + n;
            }
            Cg[idx] = v;
        }
    }
}

// ---------------------------------------------------------------------------
// Row softmax over g_w (in place), applying the key mask.
// One block (256 thr) per row of 2048. Rows = BSZ*NH*SEQ = 131072.
// ---------------------------------------------------------------------------
__global__ void __launch_bounds__(256)
softmax_kernel(float* __restrict__ W, const int* __restrict__ mask)
{
    const size_t row = blockIdx.x;
    const int b = (int)(row / ((size_t)NH * SEQ));
    float* p = W + row * SEQ;
    const int* mrow = mask + (size_t)b * SEQ;
    const int tid = threadIdx.x;

    float4 vals[2];
    float mx = -INFINITY;
    #pragma unroll
    for (int it = 0; it < 2; it++) {
        const int k = (it*256 + tid) * 4;
        float4 v = *reinterpret_cast<const float4*>(p + k);
        if (mrow[k+0] == 0) v.x = -INFINITY;
        if (mrow[k+1] == 0) v.y = -INFINITY;
        if (mrow[k+2] == 0) v.z = -INFINITY;
        if (mrow[k+3] == 0) v.w = -INFINITY;
        vals[it] = v;
        mx = fmaxf(mx, fmaxf(fmaxf(v.x, v.y), fmaxf(v.z, v.w)));
    }

    __shared__ float red[32];
    // block max
    #pragma unroll
    for (int o = 16; o; o >>= 1) mx = fmaxf(mx, __shfl_xor_sync(0xffffffffu, mx, o));
    if ((tid & 31) == 0) red[tid >> 5] = mx;
    __syncthreads();
    if (tid < 32) {
        float v = (tid < 8) ? red[tid] : -INFINITY;
        #pragma unroll
        for (int o = 4; o; o >>= 1) v = fmaxf(v, __shfl_xor_sync(0xffffffffu, v, o));
        red[tid] = v;
    }
    __syncthreads();
    mx = red[0];
    __syncthreads();

    float sum = 0.f;
    #pragma unroll
    for (int it = 0; it < 2; it++) {
        float4 v = vals[it];
        v.x = __expf(v.x - mx); v.y = __expf(v.y - mx);
        v.z = __expf(v.z - mx); v.w = __expf(v.w - mx);
        vals[it] = v;
        sum += v.x + v.y + v.z + v.w;
    }
    // block sum
    #pragma unroll
    for (int o = 16; o; o >>= 1) sum += __shfl_xor_sync(0xffffffffu, sum, o);
    if ((tid & 31) == 0) red[tid >> 5] = sum;
    __syncthreads();
    if (tid < 32) {
        float v = (tid < 8) ? red[tid] : 0.f;
        #pragma unroll
        for (int o = 4; o; o >>= 1) v += __shfl_xor_sync(0xffffffffu, v, o);
        red[tid] = v;
    }
    __syncthreads();
    const float inv = 1.f / red[0];

    #pragma unroll
    for (int it = 0; it < 2; it++) {
        const int k = (it*256 + tid) * 4;
        float4 v = vals[it];
        v.x *= inv; v.y *= inv; v.z *= inv; v.w *= inv;
        *reinterpret_cast<float4*>(p + k) = v;
    }
}

// ---------------------------------------------------------------------------
// attn_scores_max: for each (b,q), argmax over k of sum_h weights[b,h,q,k].
// jnp.argmax semantics: first index on ties.
// ---------------------------------------------------------------------------
__global__ void __launch_bounds__(256)
argsum_kernel(const float* __restrict__ W, float* __restrict__ outIdx)
{
    const int bq = blockIdx.x;
    const int b = bq >> 11;
    const int q = bq & (SEQ-1);
    const float* base = W + (size_t)b * NH * SEQ * SEQ + (size_t)q * SEQ;
    const int tid = threadIdx.x;

    float best = -1.f;
    int   bidx = 0;
    for (int k = tid; k < SEQ; k += 256) {
        float s = 0.f;
        #pragma unroll
        for (int h = 0; h < NH; h++)
            s += base[(size_t)h * SEQ * SEQ + k];
        if (s > best) { best = s; bidx = k; }   // strict > keeps earliest k
    }

    __shared__ float sv[256];
    __shared__ int   si[256];
    sv[tid] = best; si[tid] = bidx;
    __syncthreads();
    for (int off = 128; off; off >>= 1) {
        if (tid < off) {
            float v2 = sv[tid + off]; int i2 = si[tid + off];
            if (v2 > sv[tid] || (v2 == sv[tid] && i2 < si[tid])) {
                sv[tid] = v2; si[tid] = i2;
            }
        }
        __syncthreads();
    }
    if (tid == 0) outIdx[bq] = (float)si[0];
}

// ---------------------------------------------------------------------------
// Launch
// ---------------------------------------------------------------------------
extern "C" void kernel_launch(void* const* d_in, const int* in_sizes, int n_in,
                              void* d_out, int out_size)
{
    const float* X    = (const float*)d_in[0];
    const int*   mask = (const int*)  d_in[1];
    const float* Wq   = (const float*)d_in[2];
    const float* bq   = (const float*)d_in[3];
    const float* Wk   = (const float*)d_in[4];
    const float* bk   = (const float*)d_in[5];
    const float* Wv   = (const float*)d_in[6];
    const float* bv   = (const float*)d_in[7];
    const float* Wo   = (const float*)d_in[8];
    const float* bo   = (const float*)d_in[9];
    float* out = (float*)d_out;

    static float *pq = nullptr, *pk = nullptr, *pvt = nullptr, *pw = nullptr, *pctx = nullptr;
    if (!pq) {
        cudaGetSymbolAddress((void**)&pq,   g_q);
        cudaGetSymbolAddress((void**)&pk,   g_k);
        cudaGetSymbolAddress((void**)&pvt,  g_vt);
        cudaGetSymbolAddress((void**)&pw,   g_w);
        cudaGetSymbolAddress((void**)&pctx, g_ctx);
    }

    const int M = BSZ * SEQ;      // 8192
    const float qscale = 1.0f / 8.0f;  // 1/sqrt(64)

    // --- QKV projections (head-major outputs) ---
    {
        dim3 grid(DIM/128, M/128, 1);
        sgemm_tn<128,128,8,8,8,OUT_QHEAD><<<grid, 256>>>(
            X, Wq, bq, pq, M, DIM, DIM, qscale, 0, 0, 0);
        sgemm_tn<128,128,8,8,8,OUT_QHEAD><<<grid, 256>>>(
            X, Wk, bk, pk, M, DIM, DIM, 1.0f, 0, 0, 0);
        sgemm_tn<128,128,8,8,8,OUT_VT><<<grid, 256>>>(
            X, Wv, bv, pvt, M, DIM, DIM, 1.0f, 0, 0, 0);
    }

    // --- Scores: per (b,h)  S = Q @ K^T  -> g_w ---
    {
        dim3 grid(SEQ/128, SEQ/128, BSZ*NH);
        sgemm_tn<128,128,8,8,8,OUT_PLAIN><<<grid, 256>>>(
            pq, pk, nullptr, pw, SEQ, SEQ, DH, 1.0f,
            (size_t)SEQ*DH, (size_t)SEQ*DH, (size_t)SEQ*SEQ);
    }

    // --- Softmax (in place, with mask) ---
    softmax_kernel<<<BSZ*NH*SEQ, 256>>>(pw, mask);

    // --- Head-sum + argmax (independent of AV; write second output) ---
    if (out_size >= BSZ*SEQ*DIM + BSZ*SEQ) {
        argsum_kernel<<<BSZ*SEQ, 256>>>(pw, out + (size_t)BSZ*SEQ*DIM);
    }

    // --- Context: per (b,h)  ctx = W @ V  (V stored transposed) ---
    {
        dim3 grid(DH/64, SEQ/128, BSZ*NH);
        sgemm_tn<128,64,16,8,4,OUT_CTX><<<grid, 256>>>(
            pw, pvt, nullptr, pctx, SEQ, DH, SEQ, 1.0f,
            (size_t)SEQ*SEQ, (size_t)DH*SEQ, 0);
    }

    // --- Output projection ---
    {
        dim3 grid(DIM/128, M/128, 1);
        sgemm_tn<128,128,8,8,8,OUT_PLAIN><<<grid, 256>>>(
            pctx, Wo, bo, out, M, DIM, DIM, 1.0f, 0, 0, 0);
    }
}

// round 2
// speedup vs baseline: 1.6429x; 1.6429x over previous
#include <cuda_runtime.h>
#include <math.h>
#include <stdint.h>

#define BSZ 4
#define SEQ 2048
#define DIM 1024
#define NH  16
#define DH  64

// ---------------------------------------------------------------------------
// Scratch (device globals; no allocations allowed)
// ---------------------------------------------------------------------------
__device__ float g_q  [(size_t)BSZ*NH*SEQ*DH];   // [b,h,s,d]
__device__ float g_k  [(size_t)BSZ*NH*SEQ*DH];   // [b,h,s,d]
__device__ float g_vt [(size_t)BSZ*NH*DH*SEQ];   // [b,h,d,s] (V transposed)
__device__ float g_w  [(size_t)BSZ*NH*SEQ*SEQ];  // attn weights, 1 GiB
__device__ float g_ctx[(size_t)BSZ*SEQ*DIM];     // [b,s,dim]

#define OUT_PLAIN 0
#define OUT_QHEAD 1
#define OUT_VT    2
#define OUT_CTX   3

// ---------------------------------------------------------------------------
// Helpers
// ---------------------------------------------------------------------------
__device__ __forceinline__ uint32_t f2tf(float x) {
    uint32_t r; asm("cvt.rna.tf32.f32 %0, %1;" : "=r"(r) : "f"(x)); return r;
}

__device__ __forceinline__ void mma8(float c[4], const uint32_t a[4], const uint32_t b[2]) {
    asm volatile(
        "mma.sync.aligned.m16n8k8.row.col.f32.tf32.tf32.f32 "
        "{%0,%1,%2,%3}, {%4,%5,%6,%7}, {%8,%9}, {%0,%1,%2,%3};"
        : "+f"(c[0]), "+f"(c[1]), "+f"(c[2]), "+f"(c[3])
        : "r"(a[0]), "r"(a[1]), "r"(a[2]), "r"(a[3]), "r"(b[0]), "r"(b[1]));
}

__device__ __forceinline__ void cpasync16(void* dst_smem, const void* src) {
    uint32_t d = (uint32_t)__cvta_generic_to_shared(dst_smem);
    asm volatile("cp.async.ca.shared.global [%0], [%1], 16;" :: "r"(d), "l"(src));
}

template<int MODE>
__device__ __forceinline__ void store_c(float* __restrict__ Cg, int z, int m, int n,
                                        int N, size_t sCz, float v)
{
    size_t idx;
    if (MODE == OUT_PLAIN) {
        idx = (size_t)z * sCz + (size_t)m * N + n;
    } else if (MODE == OUT_QHEAD) {
        int b = m >> 11, s = m & (SEQ-1);
        int h = n >> 6,  d = n & (DH-1);
        idx = (((size_t)(b*NH + h) * SEQ) + s) * DH + d;
    } else if (MODE == OUT_VT) {
        int b = m >> 11, s = m & (SEQ-1);
        int h = n >> 6,  d = n & (DH-1);
        idx = (((size_t)(b*NH + h) * DH) + d) * SEQ + s;
    } else { // OUT_CTX
        int b = z / NH, h = z % NH;
        idx = ((size_t)(b*SEQ + m)) * DIM + (size_t)h*DH + n;
    }
    Cg[idx] = v;
}

// ---------------------------------------------------------------------------
// TF32 tensor-core GEMM:  C = (A[M,K] @ B[N,K]^T + bias) * scale
// THREE=1 -> 3xTF32 (fp32-accurate): hi*hi + hi*lo + lo*hi
// ---------------------------------------------------------------------------
template<int BM, int BN, int BK, int WM, int WN, int THREE, int MODE>
__global__ void __launch_bounds__(WM*WN*32)
mma_tn(const float* __restrict__ Ag, const float* __restrict__ Bg,
       const float* __restrict__ bias, float* __restrict__ Cg,
       int M, int N, int K, float scale,
       size_t sAz, size_t sBz, size_t sCz)
{
    constexpr int NT   = WM*WN*32;
    constexpr int LDSM = BK + 4;          // padded row pitch (floats)
    constexpr int WTM  = BM/WM, WTN = BN/WN;
    constexpr int MI   = WTM/16, NI = WTN/8;

    extern __shared__ float smemf[];
    float* AsBuf[2] = { smemf,
                        smemf + (size_t)(BM+BN)*LDSM };
    float* BsBuf[2] = { smemf + (size_t)BM*LDSM,
                        smemf + (size_t)(BM+BN)*LDSM + (size_t)BM*LDSM };

    const int z = blockIdx.z;
    const float* A = Ag + (size_t)z * sAz;
    const float* B = Bg + (size_t)z * sBz;
    const int bm0 = blockIdx.y * BM;
    const int bn0 = blockIdx.x * BN;
    const int tid = threadIdx.x, lane = tid & 31, warp = tid >> 5;
    const int wm0 = (warp / WN) * WTM;
    const int wn0 = (warp % WN) * WTN;
    const int g = lane >> 2, t = lane & 3;

    float acc[MI][NI][4];
    #pragma unroll
    for (int i = 0; i < MI; i++)
        #pragma unroll
        for (int j = 0; j < NI; j++)
            #pragma unroll
            for (int r = 0; r < 4; r++) acc[i][j][r] = 0.f;

    auto load_stage = [&](int k0, int s) {
        #pragma unroll 4
        for (int i = tid; i < BM*BK/4; i += NT) {
            int row = i / (BK/4), c4 = (i % (BK/4)) * 4;
            cpasync16(&AsBuf[s][row*LDSM + c4], &A[(size_t)(bm0+row)*K + k0 + c4]);
        }
        #pragma unroll 4
        for (int i = tid; i < BN*BK/4; i += NT) {
            int row = i / (BK/4), c4 = (i % (BK/4)) * 4;
            cpasync16(&BsBuf[s][row*LDSM + c4], &B[(size_t)(bn0+row)*K + k0 + c4]);
        }
        asm volatile("cp.async.commit_group;");
    };

    const int nk = K / BK;
    load_stage(0, 0);

    for (int kt = 0; kt < nk; kt++) {
        const int s = kt & 1;
        if (kt + 1 < nk) {
            load_stage((kt+1)*BK, s ^ 1);
            asm volatile("cp.async.wait_group 1;");
        } else {
            asm volatile("cp.async.wait_group 0;");
        }
        __syncthreads();

        const float* As = AsBuf[s];
        const float* Bs = BsBuf[s];

        #pragma unroll
        for (int ks = 0; ks < BK/8; ks++) {
            const int kb = ks * 8;
            uint32_t ah[MI][4], al[MI][4];
            uint32_t bh[NI][2], bl[NI][2];

            #pragma unroll
            for (int i = 0; i < MI; i++) {
                const int r0 = wm0 + i*16 + g;
                float x0 = As[(size_t)r0     *LDSM + kb + t];
                float x1 = As[(size_t)(r0+8) *LDSM + kb + t];
                float x2 = As[(size_t)r0     *LDSM + kb + 4 + t];
                float x3 = As[(size_t)(r0+8) *LDSM + kb + 4 + t];
                ah[i][0] = f2tf(x0); ah[i][1] = f2tf(x1);
                ah[i][2] = f2tf(x2); ah[i][3] = f2tf(x3);
                if (THREE) {
                    al[i][0] = f2tf(x0 - __uint_as_float(ah[i][0]));
                    al[i][1] = f2tf(x1 - __uint_as_float(ah[i][1]));
                    al[i][2] = f2tf(x2 - __uint_as_float(ah[i][2]));
                    al[i][3] = f2tf(x3 - __uint_as_float(ah[i][3]));
                }
            }
            #pragma unroll
            for (int j = 0; j < NI; j++) {
                const int c0 = wn0 + j*8 + g;
                float y0 = Bs[(size_t)c0*LDSM + kb + t];
                float y1 = Bs[(size_t)c0*LDSM + kb + 4 + t];
                bh[j][0] = f2tf(y0); bh[j][1] = f2tf(y1);
                if (THREE) {
                    bl[j][0] = f2tf(y0 - __uint_as_float(bh[j][0]));
                    bl[j][1] = f2tf(y1 - __uint_as_float(bh[j][1]));
                }
            }

            #pragma unroll
            for (int i = 0; i < MI; i++)
                #pragma unroll
                for (int j = 0; j < NI; j++)
                    mma8(acc[i][j], ah[i], bh[j]);
            if (THREE) {
                #pragma unroll
                for (int i = 0; i < MI; i++)
                    #pragma unroll
                    for (int j = 0; j < NI; j++) {
                        mma8(acc[i][j], ah[i], bl[j]);
                        mma8(acc[i][j], al[i], bh[j]);
                    }
            }
        }
        __syncthreads();
    }

    // Epilogue
    #pragma unroll
    for (int i = 0; i < MI; i++) {
        #pragma unroll
        for (int j = 0; j < NI; j++) {
            const int m0 = bm0 + wm0 + i*16 + g;
            const int n0 = bn0 + wn0 + j*8 + 2*t;
            float v0 = acc[i][j][0], v1 = acc[i][j][1];
            float v2 = acc[i][j][2], v3 = acc[i][j][3];
            if (bias) {
                v0 += bias[n0]; v1 += bias[n0+1];
                v2 += bias[n0]; v3 += bias[n0+1];
            }
            v0 *= scale; v1 *= scale; v2 *= scale; v3 *= scale;
            store_c<MODE>(Cg, z, m0,   n0,   N, sCz, v0);
            store_c<MODE>(Cg, z, m0,   n0+1, N, sCz, v1);
            store_c<MODE>(Cg, z, m0+8, n0,   N, sCz, v2);
            store_c<MODE>(Cg, z, m0+8, n0+1, N, sCz, v3);
        }
    }
}

// ---------------------------------------------------------------------------
// Row softmax over g_w (in place), applying the key mask.
// ---------------------------------------------------------------------------
__global__ void __launch_bounds__(256)
softmax_kernel(float* __restrict__ W, const int* __restrict__ mask)
{
    const size_t row = blockIdx.x;
    const int b = (int)(row / ((size_t)NH * SEQ));
    float* p = W + row * SEQ;
    const int* mrow = mask + (size_t)b * SEQ;
    const int tid = threadIdx.x;

    float4 vals[2];
    float mx = -INFINITY;
    #pragma unroll
    for (int it = 0; it < 2; it++) {
        const int k = (it*256 + tid) * 4;
        float4 v = *reinterpret_cast<const float4*>(p + k);
        if (mrow[k+0] == 0) v.x = -INFINITY;
        if (mrow[k+1] == 0) v.y = -INFINITY;
        if (mrow[k+2] == 0) v.z = -INFINITY;
        if (mrow[k+3] == 0) v.w = -INFINITY;
        vals[it] = v;
        mx = fmaxf(mx, fmaxf(fmaxf(v.x, v.y), fmaxf(v.z, v.w)));
    }

    __shared__ float red[32];
    #pragma unroll
    for (int o = 16; o; o >>= 1) mx = fmaxf(mx, __shfl_xor_sync(0xffffffffu, mx, o));
    if ((tid & 31) == 0) red[tid >> 5] = mx;
    __syncthreads();
    if (tid < 32) {
        float v = (tid < 8) ? red[tid] : -INFINITY;
        #pragma unroll
        for (int o = 4; o; o >>= 1) v = fmaxf(v, __shfl_xor_sync(0xffffffffu, v, o));
        red[tid] = v;
    }
    __syncthreads();
    mx = red[0];
    __syncthreads();

    float sum = 0.f;
    #pragma unroll
    for (int it = 0; it < 2; it++) {
        float4 v = vals[it];
        v.x = __expf(v.x - mx); v.y = __expf(v.y - mx);
        v.z = __expf(v.z - mx); v.w = __expf(v.w - mx);
        vals[it] = v;
        sum += v.x + v.y + v.z + v.w;
    }
    #pragma unroll
    for (int o = 16; o; o >>= 1) sum += __shfl_xor_sync(0xffffffffu, sum, o);
    if ((tid & 31) == 0) red[tid >> 5] = sum;
    __syncthreads();
    if (tid < 32) {
        float v = (tid < 8) ? red[tid] : 0.f;
        #pragma unroll
        for (int o = 4; o; o >>= 1) v += __shfl_xor_sync(0xffffffffu, v, o);
        red[tid] = v;
    }
    __syncthreads();
    const float inv = 1.f / red[0];

    #pragma unroll
    for (int it = 0; it < 2; it++) {
        const int k = (it*256 + tid) * 4;
        float4 v = vals[it];
        v.x *= inv; v.y *= inv; v.z *= inv; v.w *= inv;
        *reinterpret_cast<float4*>(p + k) = v;
    }
}

// ---------------------------------------------------------------------------
// attn_scores_max: argmax over k of sum_h weights[b,h,q,k] (first on ties)
// ---------------------------------------------------------------------------
__global__ void __launch_bounds__(256)
argsum_kernel(const float* __restrict__ W, float* __restrict__ outIdx)
{
    const int bq = blockIdx.x;
    const int b = bq >> 11;
    const int q = bq & (SEQ-1);
    const float* base = W + (size_t)b * NH * SEQ * SEQ + (size_t)q * SEQ;
    const int tid = threadIdx.x;

    float best = -1.f;
    int   bidx = 0;
    for (int k = tid; k < SEQ; k += 256) {
        float s = 0.f;
        #pragma unroll
        for (int h = 0; h < NH; h++)
            s += base[(size_t)h * SEQ * SEQ + k];
        if (s > best) { best = s; bidx = k; }
    }

    __shared__ float sv[256];
    __shared__ int   si[256];
    sv[tid] = best; si[tid] = bidx;
    __syncthreads();
    for (int off = 128; off; off >>= 1) {
        if (tid < off) {
            float v2 = sv[tid + off]; int i2 = si[tid + off];
            if (v2 > sv[tid] || (v2 == sv[tid] && i2 < si[tid])) {
                sv[tid] = v2; si[tid] = i2;
            }
        }
        __syncthreads();
    }
    if (tid == 0) outIdx[bq] = (float)si[0];
}

// ---------------------------------------------------------------------------
// Launch
// ---------------------------------------------------------------------------
extern "C" void kernel_launch(void* const* d_in, const int* in_sizes, int n_in,
                              void* d_out, int out_size)
{
    const float* X    = (const float*)d_in[0];
    const int*   mask = (const int*)  d_in[1];
    const float* Wq   = (const float*)d_in[2];
    const float* bq   = (const float*)d_in[3];
    const float* Wk   = (const float*)d_in[4];
    const float* bk   = (const float*)d_in[5];
    const float* Wv   = (const float*)d_in[6];
    const float* bv   = (const float*)d_in[7];
    const float* Wo   = (const float*)d_in[8];
    const float* bo   = (const float*)d_in[9];
    float* out = (float*)d_out;

    static float *pq = nullptr, *pk = nullptr, *pvt = nullptr, *pw = nullptr, *pctx = nullptr;
    if (!pq) {
        cudaGetSymbolAddress((void**)&pq,   g_q);
        cudaGetSymbolAddress((void**)&pk,   g_k);
        cudaGetSymbolAddress((void**)&pvt,  g_vt);
        cudaGetSymbolAddress((void**)&pw,   g_w);
        cudaGetSymbolAddress((void**)&pctx, g_ctx);
    }

    const int M = BSZ * SEQ;           // 8192
    const float qscale = 1.0f / 8.0f;  // 1/sqrt(64)

    constexpr int SMEM_BIG = (128 + 128) * 36 * 4 * 2;  // 73728
    constexpr int SMEM_AV  = (128 + 64)  * 36 * 4 * 2;  // 55296

    cudaFuncSetAttribute(mma_tn<128,128,32,2,4,1,OUT_QHEAD>,
                         cudaFuncAttributeMaxDynamicSharedMemorySize, SMEM_BIG);
    cudaFuncSetAttribute(mma_tn<128,128,32,2,4,0,OUT_VT>,
                         cudaFuncAttributeMaxDynamicSharedMemorySize, SMEM_BIG);
    cudaFuncSetAttribute(mma_tn<128,128,32,2,4,1,OUT_PLAIN>,
                         cudaFuncAttributeMaxDynamicSharedMemorySize, SMEM_BIG);
    cudaFuncSetAttribute(mma_tn<128,128,32,2,4,0,OUT_PLAIN>,
                         cudaFuncAttributeMaxDynamicSharedMemorySize, SMEM_BIG);
    cudaFuncSetAttribute(mma_tn<128,64,32,2,2,0,OUT_CTX>,
                         cudaFuncAttributeMaxDynamicSharedMemorySize, SMEM_AV);

    // --- QKV projections (3xTF32 for Q,K; single TF32 for V) ---
    {
        dim3 grid(DIM/128, M/128, 1);
        mma_tn<128,128,32,2,4,1,OUT_QHEAD><<<grid, 256, SMEM_BIG>>>(
            X, Wq, bq, pq, M, DIM, DIM, qscale, 0, 0, 0);
        mma_tn<128,128,32,2,4,1,OUT_QHEAD><<<grid, 256, SMEM_BIG>>>(
            X, Wk, bk, pk, M, DIM, DIM, 1.0f, 0, 0, 0);
        mma_tn<128,128,32,2,4,0,OUT_VT><<<grid, 256, SMEM_BIG>>>(
            X, Wv, bv, pvt, M, DIM, DIM, 1.0f, 0, 0, 0);
    }

    // --- Scores: per (b,h)  S = Q @ K^T  (3xTF32, argmax-critical) ---
    {
        dim3 grid(SEQ/128, SEQ/128, BSZ*NH);
        mma_tn<128,128,32,2,4,1,OUT_PLAIN><<<grid, 256, SMEM_BIG>>>(
            pq, pk, nullptr, pw, SEQ, SEQ, DH, 1.0f,
            (size_t)SEQ*DH, (size_t)SEQ*DH, (size_t)SEQ*SEQ);
    }

    // --- Softmax (in place, with mask) ---
    softmax_kernel<<<BSZ*NH*SEQ, 256>>>(pw, mask);

    // --- Head-sum + argmax (second output) ---
    if (out_size >= BSZ*SEQ*DIM + BSZ*SEQ) {
        argsum_kernel<<<BSZ*SEQ, 256>>>(pw, out + (size_t)BSZ*SEQ*DIM);
    }

    // --- Context: per (b,h)  ctx = W @ V  (single TF32) ---
    {
        dim3 grid(1, SEQ/128, BSZ*NH);
        mma_tn<128,64,32,2,2,0,OUT_CTX><<<grid, 128, SMEM_AV>>>(
            pw, pvt, nullptr, pctx, SEQ, DH, SEQ, 1.0f,
            (size_t)SEQ*SEQ, (size_t)DH*SEQ, 0);
    }

    // --- Output projection (single TF32) ---
    {
        dim3 grid(DIM/128, M/128, 1);
        mma_tn<128,128,32,2,4,0,OUT_PLAIN><<<grid, 256, SMEM_BIG>>>(
            pctx, Wo, bo, out, M, DIM, DIM, 1.0f, 0, 0, 0);
    }
}